// round 1
// baseline (speedup 1.0000x reference)
#include <cuda_runtime.h>
#include <math.h>

#define BB    4
#define CC    64
#define KK    16
#define NPTS  16384
#define WOUT  16
#define NTILE 64

// scratch (no allocations allowed)
__device__ float g_y[BB * CC * NPTS];      // pre-BN result, [B][C][N]
__device__ float g_stats[2 * CC];          // [scale[c], shift[c]]

// Main fused kernel: weights + einsum + linear -> g_y
// grid: (NPTS/NTILE, B), block: 256 threads
// dynamic smem: Wsm[16][16][64] (16384 f) + Lsm[64][68] (4352 f) + Msm[64][68] (4352 f)
__global__ __launch_bounds__(256, 2)
void sc_main(const float* __restrict__ points,
             const float* __restrict__ coord,
             const float* __restrict__ w1,
             const float* __restrict__ b1,
             const float* __restrict__ lin_w,
             const float* __restrict__ lin_b)
{
    extern __shared__ float sm[];
    float* Wsm = sm;                      // [o][k][n] : o*1024 + k*64 + n
    float* Lsm = sm + 16384;              // [kk][o2]  : kk*68 + o2
    float* Msm = sm + 16384 + 4352;       // [kk][n]   : kk*68 + n
    float* csm = Lsm;                     // coord staging [j][k][n] (3072 f), pre-loop only

    const int tid = threadIdx.x;
    const int b   = blockIdx.y;
    const int n0  = blockIdx.x * NTILE;

    // ---- stage coordinates [3][16][64] ----
#pragma unroll
    for (int i = 0; i < 12; ++i) {
        int e = tid + i * 256;            // e = j*1024 + k*64 + n
        int j = e >> 10, rem = e & 1023, k = rem >> 6, n = rem & 63;
        csm[e] = coord[(((size_t)b * 3 + j) * KK + k) * NPTS + n0 + n];
    }
    __syncthreads();

    // ---- weightnet: W[o][k][n] = relu(w1[o,:]·coord[:,k,n] + b1[o]) ----
#pragma unroll
    for (int i = 0; i < 64; ++i) {
        int e = tid + i * 256;            // e = o*1024 + k*64 + n
        int o = e >> 10, rem = e & 1023;
        float w = fmaf(__ldg(&w1[o * 3 + 0]), csm[rem],
                  fmaf(__ldg(&w1[o * 3 + 1]), csm[1024 + rem],
                  fmaf(__ldg(&w1[o * 3 + 2]), csm[2048 + rem], __ldg(&b1[o]))));
        Wsm[e] = fmaxf(w, 0.f);
    }

    const int nM  = tid & 63;             // M-compute: point within tile
    const int cg  = tid >> 6;             // M-compute: which c of the 4-chunk
    const int ng  = tid & 15;             // GEMM: n micro-tile (4 pts)
    const int o2g = tid >> 4;             // GEMM: o2 micro-tile (4 ch)

    float acc[16];
#pragma unroll
    for (int i = 0; i < 16; ++i) acc[i] = 0.f;

    for (int c0 = 0; c0 < 64; c0 += 4) {
        __syncthreads();                  // protect Lsm/Msm (and csm on iter 0)

        // stage lin_w chunk: Lsm[kk][o2] = lin_w[o2, c0*16 + kk]
#pragma unroll
        for (int i = 0; i < 16; ++i) {
            int e  = tid + i * 256;
            int kkk = e & 63, o2 = e >> 6;
            Lsm[kkk * 68 + o2] = lin_w[(size_t)o2 * 1024 + c0 * 16 + kkk];
        }

        // compute M slab: Msm[cg*16+o][n] = sum_k P[c0+cg,k,n] * W[o,k,n]
        {
            const float* pp = points + (((size_t)b * CC + (c0 + cg)) * KK) * NPTS + n0 + nM;
            float p[16];
#pragma unroll
            for (int k = 0; k < 16; ++k) p[k] = pp[(size_t)k * NPTS];
#pragma unroll
            for (int o = 0; o < 16; ++o) {
                float m = 0.f;
#pragma unroll
                for (int k = 0; k < 16; ++k)
                    m = fmaf(p[k], Wsm[o * 1024 + k * 64 + nM], m);
                Msm[(cg * 16 + o) * 68 + nM] = m;
            }
        }
        __syncthreads();

        // GEMM: acc[64 o2 x 64 n] += Lsm^T chunk * Msm chunk
#pragma unroll 16
        for (int kk = 0; kk < 64; ++kk) {
            const float4 lv = *(const float4*)(Lsm + kk * 68 + o2g * 4);
            const float4 mv = *(const float4*)(Msm + kk * 68 + ng * 4);
            const float l[4] = {lv.x, lv.y, lv.z, lv.w};
            const float m[4] = {mv.x, mv.y, mv.z, mv.w};
#pragma unroll
            for (int i = 0; i < 4; ++i)
#pragma unroll
                for (int j = 0; j < 4; ++j)
                    acc[i * 4 + j] = fmaf(l[i], m[j], acc[i * 4 + j]);
        }
    }

    // epilogue: + lin_b, write pre-BN y in [B][C][N]
#pragma unroll
    for (int i = 0; i < 4; ++i) {
        int o2 = o2g * 4 + i;
        float bias = __ldg(&lin_b[o2]);
        float4 v = make_float4(acc[i * 4 + 0] + bias, acc[i * 4 + 1] + bias,
                               acc[i * 4 + 2] + bias, acc[i * 4 + 3] + bias);
        *(float4*)&g_y[((size_t)b * CC + o2) * NPTS + n0 + ng * 4] = v;
    }
}

// Per-channel batch stats (deterministic tree reduction). grid: 64 blocks.
__global__ void sc_stats(const float* __restrict__ gamma, const float* __restrict__ beta)
{
    const int c = blockIdx.x;
    const int tid = threadIdx.x;
    float s = 0.f, q = 0.f;
    for (int i = tid; i < BB * NPTS; i += 256) {
        int b = i >> 14, n = i & (NPTS - 1);
        float v = g_y[((size_t)b * CC + c) * NPTS + n];
        s += v;
        q = fmaf(v, v, q);
    }
    __shared__ float ss[256], sq[256];
    ss[tid] = s; sq[tid] = q;
    __syncthreads();
    for (int st = 128; st > 0; st >>= 1) {
        if (tid < st) { ss[tid] += ss[tid + st]; sq[tid] += sq[tid + st]; }
        __syncthreads();
    }
    if (tid == 0) {
        const float inv = 1.f / (float)(BB * NPTS);
        float mean = ss[0] * inv;
        float var  = sq[0] * inv - mean * mean;
        float scale = rsqrtf(var + 1e-5f) * gamma[c];
        g_stats[c]      = scale;
        g_stats[CC + c] = beta[c] - mean * scale;
    }
}

// Normalize + affine + relu into d_out tail; copy xyz into d_out head.
__global__ void sc_apply(const float* __restrict__ xyz, float* __restrict__ out,
                         int off, int total)
{
    int idx = blockIdx.x * 256 + threadIdx.x;
    if (idx >= total) return;
    if (idx < off) { out[idx] = xyz[idx]; return; }
    int e = idx - off;
    int c = (e >> 14) & 63;
    float v = fmaf(g_y[e], g_stats[c], g_stats[CC + c]);
    out[idx] = fmaxf(v, 0.f);
}

extern "C" void kernel_launch(void* const* d_in, const int* in_sizes, int n_in,
                              void* d_out, int out_size)
{
    const float* xyz    = (const float*)d_in[0];
    const float* points = (const float*)d_in[1];
    const float* coord  = (const float*)d_in[2];
    const float* w1     = (const float*)d_in[3];
    const float* b1     = (const float*)d_in[4];
    const float* lin_w  = (const float*)d_in[5];
    const float* lin_b  = (const float*)d_in[6];
    const float* gamma  = (const float*)d_in[7];
    const float* beta   = (const float*)d_in[8];

    const int smem_bytes = (16384 + 4352 + 4352) * 4;  // 100352
    cudaFuncSetAttribute((const void*)sc_main,
                         cudaFuncAttributeMaxDynamicSharedMemorySize, smem_bytes);

    sc_main<<<dim3(NPTS / NTILE, BB), 256, smem_bytes>>>(points, coord, w1, b1, lin_w, lin_b);
    sc_stats<<<CC, 256>>>(gamma, beta);

    int off = out_size - BB * CC * NPTS;   // xyz prefix length (expect 196608)
    if (off < 0) off = 0;
    sc_apply<<<(out_size + 255) / 256, 256>>>(xyz, (float*)d_out, off, out_size);
}

// round 2
// speedup vs baseline: 1.0031x; 1.0031x over previous
#include <cuda_runtime.h>
#include <math.h>

#define BB    4
#define CC    64
#define KK    16
#define NPTS  16384
#define WOUT  16
#define NTILE 64

// scratch (no allocations allowed)
__device__ float g_y[BB * CC * NPTS];      // pre-BN result, [B][C][N]
__device__ float g_stats[2 * CC];          // [scale[c], shift[c]]

// Main fused kernel: weights + einsum + linear -> g_y
// grid: (NPTS/NTILE, B), block: 256 threads
// dynamic smem: Wsm[16][16][64] (16384 f) + Lsm[64][68] (4352 f) + Msm[64][68] (4352 f)
__global__ __launch_bounds__(256, 2)
void sc_main(const float* __restrict__ points,
             const float* __restrict__ coord,
             const float* __restrict__ w1,
             const float* __restrict__ b1,
             const float* __restrict__ lin_w,
             const float* __restrict__ lin_b)
{
    extern __shared__ float sm[];
    float* Wsm = sm;                      // [o][k][n] : o*1024 + k*64 + n
    float* Lsm = sm + 16384;              // [kk][o2]  : kk*68 + o2
    float* Msm = sm + 16384 + 4352;       // [kk][n]   : kk*68 + n
    float* csm = Lsm;                     // coord staging [j][k][n] (3072 f), pre-loop only

    const int tid = threadIdx.x;
    const int b   = blockIdx.y;
    const int n0  = blockIdx.x * NTILE;

    // ---- stage coordinates [3][16][64] ----
#pragma unroll
    for (int i = 0; i < 12; ++i) {
        int e = tid + i * 256;            // e = j*1024 + k*64 + n
        int j = e >> 10, rem = e & 1023, k = rem >> 6, n = rem & 63;
        csm[e] = coord[(((size_t)b * 3 + j) * KK + k) * NPTS + n0 + n];
    }
    __syncthreads();

    // ---- weightnet: W[o][k][n] = relu(w1[o,:]·coord[:,k,n] + b1[o]) ----
#pragma unroll
    for (int i = 0; i < 64; ++i) {
        int e = tid + i * 256;            // e = o*1024 + k*64 + n
        int o = e >> 10, rem = e & 1023;
        float w = fmaf(__ldg(&w1[o * 3 + 0]), csm[rem],
                  fmaf(__ldg(&w1[o * 3 + 1]), csm[1024 + rem],
                  fmaf(__ldg(&w1[o * 3 + 2]), csm[2048 + rem], __ldg(&b1[o]))));
        Wsm[e] = fmaxf(w, 0.f);
    }

    const int nM  = tid & 63;             // M-compute: point within tile
    const int cg  = tid >> 6;             // M-compute: which c of the 4-chunk
    const int ng  = tid & 15;             // GEMM: n micro-tile (4 pts)
    const int o2g = tid >> 4;             // GEMM: o2 micro-tile (4 ch)

    float acc[16];
#pragma unroll
    for (int i = 0; i < 16; ++i) acc[i] = 0.f;

    for (int c0 = 0; c0 < 64; c0 += 4) {
        __syncthreads();                  // protect Lsm/Msm (and csm on iter 0)

        // stage lin_w chunk: Lsm[kk][o2] = lin_w[o2, c0*16 + kk]
#pragma unroll
        for (int i = 0; i < 16; ++i) {
            int e  = tid + i * 256;
            int kkk = e & 63, o2 = e >> 6;
            Lsm[kkk * 68 + o2] = lin_w[(size_t)o2 * 1024 + c0 * 16 + kkk];
        }

        // compute M slab: Msm[cg*16+o][n] = sum_k P[c0+cg,k,n] * W[o,k,n]
        {
            const float* pp = points + (((size_t)b * CC + (c0 + cg)) * KK) * NPTS + n0 + nM;
            float p[16];
#pragma unroll
            for (int k = 0; k < 16; ++k) p[k] = pp[(size_t)k * NPTS];
#pragma unroll
            for (int o = 0; o < 16; ++o) {
                float m = 0.f;
#pragma unroll
                for (int k = 0; k < 16; ++k)
                    m = fmaf(p[k], Wsm[o * 1024 + k * 64 + nM], m);
                Msm[(cg * 16 + o) * 68 + nM] = m;
            }
        }
        __syncthreads();

        // GEMM: acc[64 o2 x 64 n] += Lsm^T chunk * Msm chunk
#pragma unroll 16
        for (int kk = 0; kk < 64; ++kk) {
            const float4 lv = *(const float4*)(Lsm + kk * 68 + o2g * 4);
            const float4 mv = *(const float4*)(Msm + kk * 68 + ng * 4);
            const float l[4] = {lv.x, lv.y, lv.z, lv.w};
            const float m[4] = {mv.x, mv.y, mv.z, mv.w};
#pragma unroll
            for (int i = 0; i < 4; ++i)
#pragma unroll
                for (int j = 0; j < 4; ++j)
                    acc[i * 4 + j] = fmaf(l[i], m[j], acc[i * 4 + j]);
        }
    }

    // epilogue: + lin_b, write pre-BN y in [B][C][N]
#pragma unroll
    for (int i = 0; i < 4; ++i) {
        int o2 = o2g * 4 + i;
        float bias = __ldg(&lin_b[o2]);
        float4 v = make_float4(acc[i * 4 + 0] + bias, acc[i * 4 + 1] + bias,
                               acc[i * 4 + 2] + bias, acc[i * 4 + 3] + bias);
        *(float4*)&g_y[((size_t)b * CC + o2) * NPTS + n0 + ng * 4] = v;
    }
}

// Per-channel batch stats (deterministic tree reduction). grid: 64 blocks.
__global__ void sc_stats(const float* __restrict__ gamma, const float* __restrict__ beta)
{
    const int c = blockIdx.x;
    const int tid = threadIdx.x;
    float s = 0.f, q = 0.f;
    for (int i = tid; i < BB * NPTS; i += 256) {
        int b = i >> 14, n = i & (NPTS - 1);
        float v = g_y[((size_t)b * CC + c) * NPTS + n];
        s += v;
        q = fmaf(v, v, q);
    }
    __shared__ float ss[256], sq[256];
    ss[tid] = s; sq[tid] = q;
    __syncthreads();
    for (int st = 128; st > 0; st >>= 1) {
        if (tid < st) { ss[tid] += ss[tid + st]; sq[tid] += sq[tid + st]; }
        __syncthreads();
    }
    if (tid == 0) {
        const float inv = 1.f / (float)(BB * NPTS);
        float mean = ss[0] * inv;
        float var  = sq[0] * inv - mean * mean;
        float scale = rsqrtf(var + 1e-5f) * gamma[c];
        g_stats[c]      = scale;
        g_stats[CC + c] = beta[c] - mean * scale;
    }
}

// Normalize + affine + relu into d_out tail; copy xyz into d_out head.
__global__ void sc_apply(const float* __restrict__ xyz, float* __restrict__ out,
                         int off, int total)
{
    int idx = blockIdx.x * 256 + threadIdx.x;
    if (idx >= total) return;
    if (idx < off) { out[idx] = xyz[idx]; return; }
    int e = idx - off;
    int c = (e >> 14) & 63;
    float v = fmaf(g_y[e], g_stats[c], g_stats[CC + c]);
    out[idx] = fmaxf(v, 0.f);
}

extern "C" void kernel_launch(void* const* d_in, const int* in_sizes, int n_in,
                              void* d_out, int out_size)
{
    const float* xyz    = (const float*)d_in[0];
    const float* points = (const float*)d_in[1];
    const float* coord  = (const float*)d_in[2];
    const float* w1     = (const float*)d_in[3];
    const float* b1     = (const float*)d_in[4];
    const float* lin_w  = (const float*)d_in[5];
    const float* lin_b  = (const float*)d_in[6];
    const float* gamma  = (const float*)d_in[7];
    const float* beta   = (const float*)d_in[8];

    const int smem_bytes = (16384 + 4352 + 4352) * 4;  // 100352
    cudaFuncSetAttribute((const void*)sc_main,
                         cudaFuncAttributeMaxDynamicSharedMemorySize, smem_bytes);

    sc_main<<<dim3(NPTS / NTILE, BB), 256, smem_bytes>>>(points, coord, w1, b1, lin_w, lin_b);
    sc_stats<<<CC, 256>>>(gamma, beta);

    int off = out_size - BB * CC * NPTS;   // xyz prefix length (expect 196608)
    if (off < 0) off = 0;
    sc_apply<<<(out_size + 255) / 256, 256>>>(xyz, (float*)d_out, off, out_size);
}

// round 5
// speedup vs baseline: 1.7422x; 1.7368x over previous
#include <cuda_runtime.h>
#include <math.h>
#include <stdint.h>

#define BB    4
#define CC    64
#define KK    16
#define NPTS  16384
#define NTILE 64

// ---------------- scratch (no allocations allowed) ----------------
__device__ float g_y[BB * CC * NPTS];      // pre-BN result, [B][C][N] (16.7 MB)
__device__ float g_part[CC * 8 * 2];       // per-(c, seg) partial {sum, sumsq}
__device__ float g_stats[2 * CC];          // [scale[c]], [shift[c]]

// ---------------- helpers ----------------
__device__ __forceinline__ uint32_t f2tf(float f) {
    uint32_t u; asm("cvt.rna.tf32.f32 %0, %1;" : "=r"(u) : "f"(f)); return u;
}
__device__ __forceinline__ void mma8(float& c0, float& c1, float& c2, float& c3,
                                     uint32_t a0, uint32_t a1, uint32_t a2, uint32_t a3,
                                     uint32_t b0, uint32_t b1) {
    asm volatile("mma.sync.aligned.m16n8k8.row.col.f32.tf32.tf32.f32 "
                 "{%0,%1,%2,%3},{%4,%5,%6,%7},{%8,%9},{%0,%1,%2,%3};"
                 : "+f"(c0), "+f"(c1), "+f"(c2), "+f"(c3)
                 : "r"(a0), "r"(a1), "r"(a2), "r"(a3), "r"(b0), "r"(b1));
}
#define BAR_SYNC(id, cnt)   asm volatile("bar.sync %0, %1;"   :: "r"(id), "r"(cnt) : "memory")
#define BAR_ARRIVE(id, cnt) asm volatile("bar.arrive %0, %1;" :: "r"(id), "r"(cnt) : "memory")

// smem float-offset map (total 34560 floats = 138240 B)
// Wsm [64 n][260]          @ 0      (16640 f)  row = 256 W floats (o*16+k) + pad4
// Msm [buf][32 prow][136]  @ 16640  (2 x 4352) pairs (k, k+4) interleaved along n
// Lsm [buf][64 o2][72]     @ 25344  (2 x 4608) k-permuted: block*8 + 2*(p%4) + (p/4)
#define WS      0
#define MS(b)   (16640 + (b) * 4352)
#define LS(b)   (25344 + (b) * 4608)
#define SMEMF   34560

// named barriers: FULL0=1 FULL1=2 EMPTY0=3 EMPTY1=4 CONS=5
// ================= main fused kernel =================
// grid (256, 4), 256 threads. Warps 0-3: einsum producers. Warps 4-7: MMA consumers.
__global__ __launch_bounds__(256, 1)
void sc_main(const float* __restrict__ points,
             const float* __restrict__ coord,
             const float* __restrict__ w1,
             const float* __restrict__ b1,
             const float* __restrict__ lin_w,
             const float* __restrict__ lin_b)
{
    extern __shared__ float sm[];
    const int tid = threadIdx.x;
    const int b   = blockIdx.y;
    const int n0  = blockIdx.x * NTILE;

    // ---- stage coord [3][16][64] into Msm region (free pre-loop) ----
    float* csm = sm + MS(0);
#pragma unroll
    for (int i = 0; i < 12; ++i) {
        int e = tid + i * 256;                 // e = j*1024 + k*64 + n
        int j = e >> 10, r = e & 1023;
        csm[e] = coord[(((size_t)b * 3 + j) * KK + (r >> 6)) * NPTS + n0 + (r & 63)];
    }
    __syncthreads();

    // ---- weightnet into Wsm[n][o*16+k] ----
    {
        const int n = tid & 63, q = tid >> 6;
#pragma unroll 8
        for (int jj = 0; jj < 64; ++jj) {
            int j = q * 64 + jj, o = j >> 4, k = j & 15;
            float w = fmaf(__ldg(&w1[o * 3 + 0]), csm[k * 64 + n],
                      fmaf(__ldg(&w1[o * 3 + 1]), csm[1024 + k * 64 + n],
                      fmaf(__ldg(&w1[o * 3 + 2]), csm[2048 + k * 64 + n], __ldg(&b1[o]))));
            sm[WS + n * 260 + j] = fmaxf(w, 0.f);
        }
    }
    __syncthreads();

    if (tid < 128) {
        // ================= producers: einsum =================
        const int n  = tid & 63;
        const int og = tid >> 6;               // o-half: 0 -> o 0-7, 1 -> o 8-15
        for (int ci = 0; ci < 16; ++ci) {
            const int buf = ci & 1, c0k = ci * 4;
            if (ci >= 2) BAR_SYNC(3 + buf, 256);

            // load P[4c][16k] (both og halves load same data; L2 dedups)
            float P[64];
            const float* pp = points + (((size_t)b * CC + c0k) * KK) * NPTS + n0 + n;
#pragma unroll
            for (int ck = 0; ck < 64; ++ck) P[ck] = pp[(size_t)ck * NPTS];

            float macc[32];
#pragma unroll
            for (int i = 0; i < 32; ++i) macc[i] = 0.f;

#pragma unroll
            for (int os = 0; os < 8; ++os) {
                const int o = og * 8 + os;
                const float4 w0 = *(const float4*)&sm[WS + n * 260 + o * 16 + 0];
                const float4 w4 = *(const float4*)&sm[WS + n * 260 + o * 16 + 4];
                const float4 w8 = *(const float4*)&sm[WS + n * 260 + o * 16 + 8];
                const float4 wc = *(const float4*)&sm[WS + n * 260 + o * 16 + 12];
                const float wr[16] = {w0.x,w0.y,w0.z,w0.w, w4.x,w4.y,w4.z,w4.w,
                                      w8.x,w8.y,w8.z,w8.w, wc.x,wc.y,wc.z,wc.w};
#pragma unroll
                for (int k = 0; k < 16; ++k)
#pragma unroll
                    for (int c = 0; c < 4; ++c)
                        macc[c * 8 + os] = fmaf(P[c * 16 + k], wr[k], macc[c * 8 + os]);
            }

            // store pairs (o, o+4) -> Msm[buf][prow][2n..2n+1], tf32
            float* M = sm + MS(buf);
#pragma unroll
            for (int c = 0; c < 4; ++c)
#pragma unroll
                for (int p = 0; p < 4; ++p) {
                    const int prow = (c * 2 + og) * 4 + p;
                    uint2 v = make_uint2(f2tf(macc[c * 8 + p]), f2tf(macc[c * 8 + p + 4]));
                    *(uint2*)&M[prow * 136 + 2 * n] = v;
                }
            BAR_ARRIVE(1 + buf, 256);
        }
    } else {
        // ================= consumers: L-fill + MMA =================
        const int t    = tid - 128;
        const int wm   = (tid >> 5) - 4;       // m-tile (o2 block of 16)
        const int lane = tid & 31;
        const int g    = lane >> 2, tg = lane & 3;

        float acc[8][4];
#pragma unroll
        for (int nt = 0; nt < 8; ++nt)
#pragma unroll
            for (int i = 0; i < 4; ++i) acc[nt][i] = 0.f;

        for (int ci = 0; ci < 16; ++ci) {
            const int buf = ci & 1, c0k = ci * 4;
            float* L = sm + LS(buf);
            // fill Lsm: lin_w[o2][c0k*16 .. +63], k-permuted pairs, tf32
#pragma unroll
            for (int i = 0; i < 4; ++i) {
                const int idx = t + i * 128;   // 512 = 64 rows x 8 blocks
                const int row = idx >> 3, blk = idx & 7;
                const float* src = lin_w + (size_t)row * 1024 + c0k * 16 + blk * 8;
                const float4 v0 = *(const float4*)src;
                const float4 v1 = *(const float4*)(src + 4);
                const float lo[4] = {v0.x, v0.y, v0.z, v0.w};
                const float hi[4] = {v1.x, v1.y, v1.z, v1.w};
#pragma unroll
                for (int p = 0; p < 4; ++p) {
                    uint2 u = make_uint2(f2tf(lo[p]), f2tf(hi[p]));
                    *(uint2*)&L[row * 72 + blk * 8 + 2 * p] = u;
                }
            }
            BAR_SYNC(1 + buf, 256);

            const float* M = sm + MS(buf);
#pragma unroll
            for (int ks = 0; ks < 8; ++ks) {
                const uint2 aLo = *(const uint2*)&L[(wm * 16 + g) * 72 + ks * 8 + 2 * tg];
                const uint2 aHi = *(const uint2*)&L[(wm * 16 + g + 8) * 72 + ks * 8 + 2 * tg];
#pragma unroll
                for (int nt = 0; nt < 8; ++nt) {
                    const uint2 bv = *(const uint2*)&M[(ks * 4 + tg) * 136 + 2 * (nt * 8 + g)];
                    mma8(acc[nt][0], acc[nt][1], acc[nt][2], acc[nt][3],
                         aLo.x, aHi.x, aLo.y, aHi.y, bv.x, bv.y);
                }
            }
            BAR_SYNC(5, 128);
            BAR_ARRIVE(3 + buf, 256);
        }

        // epilogue: C -> g_y (+ lin_b)
        const int r0 = wm * 16 + g, r1 = r0 + 8;
        const float bias0 = __ldg(&lin_b[r0]), bias1 = __ldg(&lin_b[r1]);
        float* y0 = g_y + ((size_t)b * CC + r0) * NPTS + n0 + tg * 2;
        float* y1 = g_y + ((size_t)b * CC + r1) * NPTS + n0 + tg * 2;
#pragma unroll
        for (int nt = 0; nt < 8; ++nt) {
            *(float2*)(y0 + nt * 8) = make_float2(acc[nt][0] + bias0, acc[nt][1] + bias0);
            *(float2*)(y1 + nt * 8) = make_float2(acc[nt][2] + bias1, acc[nt][3] + bias1);
        }
    }
}

// ================= BN tail =================
__global__ void sc_part()
{
    const int c = blockIdx.y, seg = blockIdx.x, tid = threadIdx.x;
    float s = 0.f, q = 0.f;
#pragma unroll
    for (int i = 0; i < 8; ++i) {
        int t = tid + i * 256;
        int flat = seg * 8192 + t * 4;
        int bb = flat >> 14, n = flat & (NPTS - 1);
        float4 v = *(const float4*)&g_y[(((size_t)bb * CC + c) << 14) + n];
        s += v.x + v.y + v.z + v.w;
        q = fmaf(v.x, v.x, fmaf(v.y, v.y, fmaf(v.z, v.z, fmaf(v.w, v.w, q))));
    }
    __shared__ float ss[256], sq[256];
    ss[tid] = s; sq[tid] = q;
    __syncthreads();
    for (int st = 128; st > 0; st >>= 1) {
        if (tid < st) { ss[tid] += ss[tid + st]; sq[tid] += sq[tid + st]; }
        __syncthreads();
    }
    if (tid == 0) { g_part[(c * 8 + seg) * 2] = ss[0]; g_part[(c * 8 + seg) * 2 + 1] = sq[0]; }
}

__global__ void sc_fin(const float* __restrict__ gamma, const float* __restrict__ beta)
{
    int c = threadIdx.x;
    if (c >= CC) return;
    float s = 0.f, q = 0.f;
#pragma unroll
    for (int i = 0; i < 8; ++i) { s += g_part[(c * 8 + i) * 2]; q += g_part[(c * 8 + i) * 2 + 1]; }
    const float inv = 1.f / (float)(BB * NPTS);
    float mean = s * inv;
    float var  = q * inv - mean * mean;
    float scale = rsqrtf(var + 1e-5f) * gamma[c];
    g_stats[c]      = scale;
    g_stats[CC + c] = beta[c] - mean * scale;
}

__global__ void sc_apply(const float* __restrict__ xyz, float* __restrict__ out,
                         int off4, int total4)
{
    int i4 = blockIdx.x * 256 + threadIdx.x;
    if (i4 >= total4) return;
    float4* o4 = (float4*)out;
    if (i4 < off4) { o4[i4] = ((const float4*)xyz)[i4]; return; }
    int e4 = i4 - off4;
    int c = (e4 >> 12) & 63;
    float sc = g_stats[c], sh = g_stats[CC + c];
    float4 v = ((const float4*)g_y)[e4];
    v.x = fmaxf(fmaf(v.x, sc, sh), 0.f);
    v.y = fmaxf(fmaf(v.y, sc, sh), 0.f);
    v.z = fmaxf(fmaf(v.z, sc, sh), 0.f);
    v.w = fmaxf(fmaf(v.w, sc, sh), 0.f);
    o4[i4] = v;
}

extern "C" void kernel_launch(void* const* d_in, const int* in_sizes, int n_in,
                              void* d_out, int out_size)
{
    const float* xyz    = (const float*)d_in[0];
    const float* points = (const float*)d_in[1];
    const float* coord  = (const float*)d_in[2];
    const float* w1     = (const float*)d_in[3];
    const float* b1     = (const float*)d_in[4];
    const float* lin_w  = (const float*)d_in[5];
    const float* lin_b  = (const float*)d_in[6];
    const float* gamma  = (const float*)d_in[7];
    const float* beta   = (const float*)d_in[8];

    const int smem_bytes = SMEMF * 4;  // 138240
    cudaFuncSetAttribute((const void*)sc_main,
                         cudaFuncAttributeMaxDynamicSharedMemorySize, smem_bytes);

    sc_main<<<dim3(NPTS / NTILE, BB), 256, smem_bytes>>>(points, coord, w1, b1, lin_w, lin_b);
    sc_part<<<dim3(8, CC), 256>>>();
    sc_fin<<<1, 64>>>(gamma, beta);

    int off = out_size - BB * CC * NPTS;
    if (off < 0) off = 0;
    int total4 = out_size / 4;
    sc_apply<<<(total4 + 255) / 256, 256>>>(xyz, (float*)d_out, off / 4, total4);
}